// round 1
// baseline (speedup 1.0000x reference)
#include <cuda_runtime.h>
#include <cstdint>

#define M_NODES 50000
#define N_NODES 50000
#define E_EDGES 800000
#define K_DIM   256
#define HID     256
#define HEADS   8
#define HEAD_C  32
#define RMS_EPS 1.1920929e-7f

// ---------------- scratch (static device arrays; no allocations) ----------
__device__ float g_qn[(size_t)M_NODES * HID];   // normalized q
__device__ float g_kn[(size_t)N_NODES * HID];   // normalized k
__device__ float g_v [(size_t)N_NODES * HID];   // v
__device__ float g_y [(size_t)M_NODES * HID];   // attention output
__device__ int   g_deg[M_NODES];
__device__ int   g_cur[M_NODES];
__device__ int   g_off[M_NODES + 1];
__device__ int   g_col[E_EDGES];
__device__ int   g_is64;

// ---------------- edge dtype detection (int64 vs int32) -------------------
__global__ void detect_kernel(const unsigned* __restrict__ w) {
    __shared__ int nz;
    if (threadIdx.x == 0) nz = 0;
    __syncthreads();
    // If edges are int64: odd 32-bit words are high halves of values in
    // [0, 50000) -> all zero. If int32: odd words are j indices, mostly nonzero.
    unsigned v = w[2 * threadIdx.x + 1];
    if (v != 0u) atomicAdd(&nz, 1);
    __syncthreads();
    if (threadIdx.x == 0) g_is64 = (nz == 0) ? 1 : 0;
}

// ---------------- CSR build ----------------------------------------------
__global__ void zero_counts() {
    int i = blockIdx.x * blockDim.x + threadIdx.x;
    if (i < M_NODES) { g_deg[i] = 0; g_cur[i] = 0; }
}

__global__ void count_edges(const int* __restrict__ ew) {
    int e = blockIdx.x * blockDim.x + threadIdx.x;
    if (e >= E_EDGES) return;
    int i = g_is64 ? ew[4 * e] : ew[2 * e];
    atomicAdd(&g_deg[i], 1);
}

__global__ void scan_kernel() {  // single block, 1024 threads
    __shared__ int sh_warp[32];
    __shared__ int sh_carry;
    int lane = threadIdx.x & 31;
    int wid  = threadIdx.x >> 5;
    if (threadIdx.x == 0) { sh_carry = 0; g_off[0] = 0; }
    __syncthreads();
    for (int base = 0; base < M_NODES; base += 1024) {
        int idx = base + threadIdx.x;
        int v = (idx < M_NODES) ? g_deg[idx] : 0;
        int x = v;
        #pragma unroll
        for (int d = 1; d < 32; d <<= 1) {
            int t = __shfl_up_sync(0xFFFFFFFFu, x, d);
            if (lane >= d) x += t;
        }
        if (lane == 31) sh_warp[wid] = x;
        __syncthreads();
        if (wid == 0) {
            int y = sh_warp[lane];
            #pragma unroll
            for (int d = 1; d < 32; d <<= 1) {
                int t = __shfl_up_sync(0xFFFFFFFFu, y, d);
                if (lane >= d) y += t;
            }
            sh_warp[lane] = y;
        }
        __syncthreads();
        int prefix = sh_carry + (wid > 0 ? sh_warp[wid - 1] : 0);
        int incl = prefix + x;
        if (idx < M_NODES) g_off[idx + 1] = incl;
        __syncthreads();
        if (threadIdx.x == 1023) sh_carry += sh_warp[31];
        __syncthreads();
    }
}

__global__ void fill_edges(const int* __restrict__ ew) {
    int e = blockIdx.x * blockDim.x + threadIdx.x;
    if (e >= E_EDGES) return;
    int i, j;
    if (g_is64) { i = ew[4 * e]; j = ew[4 * e + 2]; }
    else        { i = ew[2 * e]; j = ew[2 * e + 1]; }
    int p = atomicAdd(&g_cur[i], 1);
    g_col[g_off[i] + p] = j;
}

// ---------------- fused GEMM (+bias, +per-head RMS norm) -------------------
// C[m, n] = sum_k A[m,k] * W[n,k] + bias[n], optional RMS norm per 32-col chunk.
// mode 0: plain -> outA (stride HID)
// mode 1: norm all cols -> outA (stride HID)
// mode 2: cols < HID normed -> outA; cols >= HID plain -> outB (both stride HID)
#define BM 128
#define BN 64
#define BK 32

__global__ __launch_bounds__(256) void gemm_kernel(
    const float* __restrict__ A, const float* __restrict__ W,
    const float* __restrict__ bias,
    float* __restrict__ outA, float* __restrict__ outB,
    int Mrows, int mode)
{
    __shared__ float As[BK][BM + 1];
    __shared__ float Ws[BK][BN + 1];

    int tid = threadIdx.x;
    int tx = tid & 15;        // 16 threads over N (TN=4)
    int ty = tid >> 4;        // 16 threads over M (TM=8)
    int m0 = blockIdx.x * BM;
    int n0 = blockIdx.y * BN;

    float acc[8][4];
    #pragma unroll
    for (int i = 0; i < 8; i++)
        #pragma unroll
        for (int j = 0; j < 4; j++) acc[i][j] = 0.f;

    for (int k0 = 0; k0 < K_DIM; k0 += BK) {
        // load A tile [BM x BK], store transposed As[k][row]
        #pragma unroll
        for (int q = 0; q < 4; q++) {
            int id  = q * 256 + tid;       // 0..1023 float4 slots
            int row = id >> 3;
            int c4  = id & 7;
            int gr  = m0 + row;
            float4 val = make_float4(0.f, 0.f, 0.f, 0.f);
            if (gr < Mrows)
                val = *(const float4*)&A[(size_t)gr * K_DIM + k0 + c4 * 4];
            As[c4 * 4 + 0][row] = val.x;
            As[c4 * 4 + 1][row] = val.y;
            As[c4 * 4 + 2][row] = val.z;
            As[c4 * 4 + 3][row] = val.w;
        }
        // load W tile [BN x BK], store transposed Ws[k][n]
        #pragma unroll
        for (int q = 0; q < 2; q++) {
            int id = q * 256 + tid;        // 0..511 float4 slots
            int n  = id >> 3;
            int c4 = id & 7;
            float4 val = *(const float4*)&W[(size_t)(n0 + n) * K_DIM + k0 + c4 * 4];
            Ws[c4 * 4 + 0][n] = val.x;
            Ws[c4 * 4 + 1][n] = val.y;
            Ws[c4 * 4 + 2][n] = val.z;
            Ws[c4 * 4 + 3][n] = val.w;
        }
        __syncthreads();
        #pragma unroll
        for (int kk = 0; kk < BK; kk++) {
            float a[8], b[4];
            #pragma unroll
            for (int i = 0; i < 8; i++) a[i] = As[kk][ty * 8 + i];
            #pragma unroll
            for (int j = 0; j < 4; j++) b[j] = Ws[kk][tx * 4 + j];
            #pragma unroll
            for (int i = 0; i < 8; i++)
                #pragma unroll
                for (int j = 0; j < 4; j++)
                    acc[i][j] = fmaf(a[i], b[j], acc[i][j]);
        }
        __syncthreads();
    }

    // bias
    float bb[4];
    #pragma unroll
    for (int j = 0; j < 4; j++) bb[j] = bias[n0 + tx * 4 + j];
    #pragma unroll
    for (int i = 0; i < 8; i++)
        #pragma unroll
        for (int j = 0; j < 4; j++) acc[i][j] += bb[j];

    // per-head RMS norm: each 32-col chunk is owned by an 8-thread tx group
    bool donorm = (mode == 1) || (mode == 2 && n0 < HID);
    if (donorm) {
        #pragma unroll
        for (int i = 0; i < 8; i++) {
            float p = acc[i][0] * acc[i][0] + acc[i][1] * acc[i][1]
                    + acc[i][2] * acc[i][2] + acc[i][3] * acc[i][3];
            p += __shfl_xor_sync(0xFFFFFFFFu, p, 1);
            p += __shfl_xor_sync(0xFFFFFFFFu, p, 2);
            p += __shfl_xor_sync(0xFFFFFFFFu, p, 4);
            float r = rsqrtf(p * (1.0f / HEAD_C) + RMS_EPS);
            #pragma unroll
            for (int j = 0; j < 4; j++) acc[i][j] *= r;
        }
    }

    // store (float4, columns contiguous per thread)
    bool toB = (mode == 2) && (n0 >= HID);
    int ncol = toB ? (n0 - HID + tx * 4) : (n0 + tx * 4);
    float* outp = toB ? outB : outA;
    #pragma unroll
    for (int i = 0; i < 8; i++) {
        int gr = m0 + ty * 8 + i;
        if (gr < Mrows) {
            float4 res = make_float4(acc[i][0], acc[i][1], acc[i][2], acc[i][3]);
            *(float4*)&outp[(size_t)gr * HID + ncol] = res;
        }
    }
}

// ---------------- edge attention: one block per node, one warp per head ----
__global__ __launch_bounds__(256) void edge_kernel() {
    int i    = blockIdx.x;
    int h    = threadIdx.x >> 5;
    int lane = threadIdx.x & 31;

    int s = g_off[i];
    int e = g_off[i + 1];

    size_t qbase = (size_t)i * HID + h * HEAD_C + lane;
    float qv  = g_qn[qbase];
    float tot = 0.f;
    float acc = 0.f;
    const float scale = 0.17677669529663687f;  // 1/sqrt(32)

    for (int t = s; t < e; t++) {
        int j = g_col[t];
        size_t base = (size_t)j * HID + h * HEAD_C + lane;
        float kv = g_kn[base];
        float vv = g_v[base];
        float d = qv * kv;
        d += __shfl_xor_sync(0xFFFFFFFFu, d, 16);
        d += __shfl_xor_sync(0xFFFFFFFFu, d, 8);
        d += __shfl_xor_sync(0xFFFFFFFFu, d, 4);
        d += __shfl_xor_sync(0xFFFFFFFFu, d, 2);
        d += __shfl_xor_sync(0xFFFFFFFFu, d, 1);
        float w = __expf(d * scale);
        tot += w;
        acc = fmaf(w, vv, acc);
    }
    g_y[qbase] = (e > s) ? (acc / tot) : 0.f;
}

// ---------------- launch ---------------------------------------------------
extern "C" void kernel_launch(void* const* d_in, const int* in_sizes, int n_in,
                              void* d_out, int out_size) {
    const float* query = (const float*)d_in[0];
    const float* keys  = (const float*)d_in[1];
    const int*   edges = (const int*)d_in[2];   // raw words; dtype detected on device
    const float* Wq    = (const float*)d_in[3];
    const float* bq    = (const float*)d_in[4];
    const float* Wkv   = (const float*)d_in[5];
    const float* bkv   = (const float*)d_in[6];
    const float* Wo    = (const float*)d_in[7];
    const float* bo    = (const float*)d_in[8];
    float* out = (float*)d_out;

    float* qn = nullptr; float* kn = nullptr; float* vv = nullptr; float* y = nullptr;
    cudaGetSymbolAddress((void**)&qn, g_qn);
    cudaGetSymbolAddress((void**)&kn, g_kn);
    cudaGetSymbolAddress((void**)&vv, g_v);
    cudaGetSymbolAddress((void**)&y,  g_y);

    // CSR build
    detect_kernel<<<1, 256>>>((const unsigned*)edges);
    zero_counts<<<(M_NODES + 255) / 256, 256>>>();
    count_edges<<<(E_EDGES + 255) / 256, 256>>>(edges);
    scan_kernel<<<1, 1024>>>();
    fill_edges<<<(E_EDGES + 255) / 256, 256>>>(edges);

    dim3 gq((M_NODES + BM - 1) / BM, HID / BN);       // 391 x 4
    dim3 gkv((N_NODES + BM - 1) / BM, 2 * HID / BN);  // 391 x 8

    // q projection + bias + RMS norm
    gemm_kernel<<<gq, 256>>>(query, Wq, bq, qn, nullptr, M_NODES, 1);
    // kv projection + bias; k half normed -> kn, v half -> v
    gemm_kernel<<<gkv, 256>>>(keys, Wkv, bkv, kn, vv, N_NODES, 2);
    // edge-softmax attention (CSR, no atomics)
    edge_kernel<<<M_NODES, 256>>>();
    // output projection
    gemm_kernel<<<gq, 256>>>(y, Wo, bo, out, nullptr, M_NODES, 0);
}

// round 2
// speedup vs baseline: 1.8248x; 1.8248x over previous
#include <cuda_runtime.h>
#include <cstdint>

#define M_NODES 50000
#define N_NODES 50000
#define E_EDGES 800000
#define K_DIM   256
#define HID     256
#define HEADS   8
#define HEAD_C  32
#define RMS_EPS 1.1920929e-7f

// ---------------- scratch (static device arrays; no allocations) ----------
__device__ float g_qn[(size_t)M_NODES * HID];   // normalized q
__device__ float g_kn[(size_t)N_NODES * HID];   // normalized k
__device__ float g_v [(size_t)N_NODES * HID];   // v
__device__ float g_y [(size_t)M_NODES * HID];   // attention output
__device__ int   g_deg[M_NODES];
__device__ int   g_cur[M_NODES];
__device__ int   g_off[M_NODES + 1];
__device__ int   g_col[E_EDGES];
__device__ int   g_bsum[64];
__device__ int   g_is64;

// ---------------- edge dtype detection (int64 vs int32) -------------------
__global__ void detect_kernel(const unsigned* __restrict__ w) {
    __shared__ int nz;
    if (threadIdx.x == 0) nz = 0;
    __syncthreads();
    unsigned v = w[2 * threadIdx.x + 1];
    if (v != 0u) atomicAdd(&nz, 1);
    __syncthreads();
    if (threadIdx.x == 0) g_is64 = (nz == 0) ? 1 : 0;
}

// ---------------- CSR build ----------------------------------------------
__global__ void count_edges(const int* __restrict__ ew) {
    int e = blockIdx.x * blockDim.x + threadIdx.x;
    if (e >= E_EDGES) return;
    int i = g_is64 ? ew[4 * e] : ew[2 * e];
    atomicAdd(&g_deg[i], 1);
}

// multi-block scan: phase 1 — per-block inclusive scan + block sums
__global__ void scan1_kernel() {
    __shared__ int sh_warp[32];
    int lane = threadIdx.x & 31;
    int wid  = threadIdx.x >> 5;
    int idx  = blockIdx.x * 1024 + threadIdx.x;
    int v = (idx < M_NODES) ? g_deg[idx] : 0;
    int x = v;
    #pragma unroll
    for (int d = 1; d < 32; d <<= 1) {
        int t = __shfl_up_sync(0xFFFFFFFFu, x, d);
        if (lane >= d) x += t;
    }
    if (lane == 31) sh_warp[wid] = x;
    __syncthreads();
    if (wid == 0) {
        int y = sh_warp[lane];
        #pragma unroll
        for (int d = 1; d < 32; d <<= 1) {
            int t = __shfl_up_sync(0xFFFFFFFFu, y, d);
            if (lane >= d) y += t;
        }
        sh_warp[lane] = y;
    }
    __syncthreads();
    int incl = x + (wid > 0 ? sh_warp[wid - 1] : 0);
    if (idx < M_NODES) g_off[idx + 1] = incl;
    if (threadIdx.x == 1023) g_bsum[blockIdx.x] = incl;
}

// phase 2 — exclusive scan of block sums (single tiny block)
__global__ void scan2_kernel(int nblk) {
    __shared__ int s[64];
    int t = threadIdx.x;
    int v = (t < nblk) ? g_bsum[t] : 0;
    s[t] = v;
    __syncthreads();
    #pragma unroll
    for (int d = 1; d < 64; d <<= 1) {
        int add = (t >= d) ? s[t - d] : 0;
        __syncthreads();
        s[t] += add;
        __syncthreads();
    }
    if (t < nblk) g_bsum[t] = s[t] - v;  // exclusive
}

// phase 3 — add block offsets
__global__ void scan3_kernel() {
    int idx = blockIdx.x * 1024 + threadIdx.x;
    if (idx == 0) g_off[0] = 0;
    if (idx < M_NODES) g_off[idx + 1] += g_bsum[blockIdx.x];
}

__global__ void fill_edges(const int* __restrict__ ew) {
    int e = blockIdx.x * blockDim.x + threadIdx.x;
    if (e >= E_EDGES) return;
    int i, j;
    if (g_is64) { i = ew[4 * e]; j = ew[4 * e + 2]; }
    else        { i = ew[2 * e]; j = ew[2 * e + 1]; }
    int p = atomicAdd(&g_cur[i], 1);
    g_col[g_off[i] + p] = j;
}

// ---------------- TF32 tensor-core GEMM (+bias, +per-head RMS norm) --------
// C[m,n] = sum_k A[m,k] * W[n,k] + bias[n]
// mode 0: plain -> outA; mode 1: norm all -> outA;
// mode 2: n<HID normed -> outA, n>=HID plain -> outB (cols shifted by HID)
#define BM 128
#define BN 64
#define BK 32

__device__ __forceinline__ unsigned f2tf32(float f) {
    unsigned r;
    asm("cvt.rna.tf32.f32 %0, %1;" : "=r"(r) : "f"(f));
    return r;
}

__device__ __forceinline__ void ldsm4(unsigned r[4], unsigned addr) {
    asm volatile("ldmatrix.sync.aligned.m8n8.x4.shared.b16 {%0,%1,%2,%3}, [%4];"
                 : "=r"(r[0]), "=r"(r[1]), "=r"(r[2]), "=r"(r[3]) : "r"(addr));
}

__device__ __forceinline__ void mma_tf32(float d[4], const unsigned a[4], const unsigned b[2]) {
    asm volatile(
        "mma.sync.aligned.m16n8k8.row.col.f32.tf32.tf32.f32 "
        "{%0,%1,%2,%3}, {%4,%5,%6,%7}, {%8,%9}, {%0,%1,%2,%3};\n"
        : "+f"(d[0]), "+f"(d[1]), "+f"(d[2]), "+f"(d[3])
        : "r"(a[0]), "r"(a[1]), "r"(a[2]), "r"(a[3]), "r"(b[0]), "r"(b[1]));
}

__global__ __launch_bounds__(256, 2) void gemm_tc_kernel(
    const float* __restrict__ A, const float* __restrict__ W,
    const float* __restrict__ bias,
    float* __restrict__ outA, float* __restrict__ outB,
    int Mrows, int mode)
{
    __shared__ float As[2][BM * BK];   // swizzled: [row][chunk^(row&7)] 16B chunks
    __shared__ float Bs[2][BN * BK];

    const int tid  = threadIdx.x;
    const int lane = tid & 31;
    const int wid  = tid >> 5;
    const int wm   = (wid >> 1) * 32;   // warp m offset (0..96)
    const int wn   = (wid & 1) * 32;    // warp n offset (0/32)
    const int m0   = blockIdx.x * BM;
    const int n0   = blockIdx.y * BN;

    const int g  = lane >> 3;
    const int lr = lane & 7;

    unsigned asbase = (unsigned)__cvta_generic_to_shared(&As[0][0]);
    unsigned bsbase = (unsigned)__cvta_generic_to_shared(&Bs[0][0]);

    // precomputed ldmatrix rows
    int rowA0 = wm + (g & 1) * 8 + lr;          // mt=0 ( +16 for mt=1 )
    int rowB0 = wn + (g >> 1) * 8 + lr;         // bt=0 ( +16 for bt=1 )

    float acc[2][4][4];
    #pragma unroll
    for (int mt = 0; mt < 2; mt++)
        #pragma unroll
        for (int nt = 0; nt < 4; nt++)
            #pragma unroll
            for (int r = 0; r < 4; r++) acc[mt][nt][r] = 0.f;

    float4 ra[4], rb[2];

    // prefetch stage 0
    #pragma unroll
    for (int q = 0; q < 4; q++) {
        int id = q * 256 + tid; int row = id >> 3, c = id & 7; int gr = m0 + row;
        ra[q] = (gr < Mrows) ? *(const float4*)&A[(size_t)gr * K_DIM + c * 4]
                             : make_float4(0.f, 0.f, 0.f, 0.f);
    }
    #pragma unroll
    for (int q = 0; q < 2; q++) {
        int id = q * 256 + tid; int row = id >> 3, c = id & 7;
        rb[q] = *(const float4*)&W[(size_t)(n0 + row) * K_DIM + c * 4];
    }
    // store stage 0 (with tf32 convert + swizzle)
    #pragma unroll
    for (int q = 0; q < 4; q++) {
        int id = q * 256 + tid; int row = id >> 3, c = id & 7;
        int sc = c ^ (row & 7);
        float4 t;
        t.x = __uint_as_float(f2tf32(ra[q].x)); t.y = __uint_as_float(f2tf32(ra[q].y));
        t.z = __uint_as_float(f2tf32(ra[q].z)); t.w = __uint_as_float(f2tf32(ra[q].w));
        *(float4*)&As[0][row * BK + sc * 4] = t;
    }
    #pragma unroll
    for (int q = 0; q < 2; q++) {
        int id = q * 256 + tid; int row = id >> 3, c = id & 7;
        int sc = c ^ (row & 7);
        float4 t;
        t.x = __uint_as_float(f2tf32(rb[q].x)); t.y = __uint_as_float(f2tf32(rb[q].y));
        t.z = __uint_as_float(f2tf32(rb[q].z)); t.w = __uint_as_float(f2tf32(rb[q].w));
        *(float4*)&Bs[0][row * BK + sc * 4] = t;
    }
    __syncthreads();

    const int NSTAGE = K_DIM / BK;  // 8
    for (int s = 0; s < NSTAGE; s++) {
        int buf = s & 1;
        // prefetch next stage into regs
        if (s + 1 < NSTAGE) {
            int k0 = (s + 1) * BK;
            #pragma unroll
            for (int q = 0; q < 4; q++) {
                int id = q * 256 + tid; int row = id >> 3, c = id & 7; int gr = m0 + row;
                ra[q] = (gr < Mrows) ? *(const float4*)&A[(size_t)gr * K_DIM + k0 + c * 4]
                                     : make_float4(0.f, 0.f, 0.f, 0.f);
            }
            #pragma unroll
            for (int q = 0; q < 2; q++) {
                int id = q * 256 + tid; int row = id >> 3, c = id & 7;
                rb[q] = *(const float4*)&W[(size_t)(n0 + row) * K_DIM + k0 + c * 4];
            }
        }
        // compute on buf
        unsigned abuf = asbase + (unsigned)(buf * BM * BK * 4);
        unsigned bbuf = bsbase + (unsigned)(buf * BN * BK * 4);
        #pragma unroll
        for (int ks = 0; ks < 4; ks++) {
            unsigned af[2][4], bf[4][2];
            int cA = ks * 2 + (g >> 1);
            int cB = ks * 2 + (g & 1);
            #pragma unroll
            for (int mt = 0; mt < 2; mt++) {
                int row = rowA0 + mt * 16;
                unsigned addr = abuf + (unsigned)((row * BK + ((cA ^ (row & 7)) * 4)) * 4);
                ldsm4(af[mt], addr);
            }
            #pragma unroll
            for (int bt = 0; bt < 2; bt++) {
                int row = rowB0 + bt * 16;
                unsigned addr = bbuf + (unsigned)((row * BK + ((cB ^ (row & 7)) * 4)) * 4);
                unsigned q4[4];
                ldsm4(q4, addr);
                bf[bt * 2 + 0][0] = q4[0]; bf[bt * 2 + 0][1] = q4[1];
                bf[bt * 2 + 1][0] = q4[2]; bf[bt * 2 + 1][1] = q4[3];
            }
            #pragma unroll
            for (int mt = 0; mt < 2; mt++)
                #pragma unroll
                for (int nt = 0; nt < 4; nt++)
                    mma_tf32(acc[mt][nt], af[mt], bf[nt]);
        }
        // store next stage
        if (s + 1 < NSTAGE) {
            int nbuf = (s + 1) & 1;
            #pragma unroll
            for (int q = 0; q < 4; q++) {
                int id = q * 256 + tid; int row = id >> 3, c = id & 7;
                int sc = c ^ (row & 7);
                float4 t;
                t.x = __uint_as_float(f2tf32(ra[q].x)); t.y = __uint_as_float(f2tf32(ra[q].y));
                t.z = __uint_as_float(f2tf32(ra[q].z)); t.w = __uint_as_float(f2tf32(ra[q].w));
                *(float4*)&As[nbuf][row * BK + sc * 4] = t;
            }
            #pragma unroll
            for (int q = 0; q < 2; q++) {
                int id = q * 256 + tid; int row = id >> 3, c = id & 7;
                int sc = c ^ (row & 7);
                float4 t;
                t.x = __uint_as_float(f2tf32(rb[q].x)); t.y = __uint_as_float(f2tf32(rb[q].y));
                t.z = __uint_as_float(f2tf32(rb[q].z)); t.w = __uint_as_float(f2tf32(rb[q].w));
                *(float4*)&Bs[nbuf][row * BK + sc * 4] = t;
            }
            __syncthreads();
        }
    }

    // ---------------- epilogue: bias, per-head RMS norm, store -------------
    bool donorm = (mode == 1) || (mode == 2 && n0 < HID);
    bool toB    = (mode == 2) && (n0 >= HID);
    float* outp = toB ? outB : outA;
    int colshift = toB ? HID : 0;

    float bb[4][2];
    #pragma unroll
    for (int nt = 0; nt < 4; nt++) {
        int col = n0 + wn + nt * 8 + (lane & 3) * 2;
        bb[nt][0] = bias[col];
        bb[nt][1] = bias[col + 1];
    }

    #pragma unroll
    for (int mt = 0; mt < 2; mt++) {
        // add bias
        #pragma unroll
        for (int nt = 0; nt < 4; nt++) {
            acc[mt][nt][0] += bb[nt][0];
            acc[mt][nt][1] += bb[nt][1];
            acc[mt][nt][2] += bb[nt][0];
            acc[mt][nt][3] += bb[nt][1];
        }
        if (donorm) {
            float s0 = 0.f, s1 = 0.f;
            #pragma unroll
            for (int nt = 0; nt < 4; nt++) {
                s0 += acc[mt][nt][0] * acc[mt][nt][0] + acc[mt][nt][1] * acc[mt][nt][1];
                s1 += acc[mt][nt][2] * acc[mt][nt][2] + acc[mt][nt][3] * acc[mt][nt][3];
            }
            s0 += __shfl_xor_sync(0xFFFFFFFFu, s0, 1);
            s0 += __shfl_xor_sync(0xFFFFFFFFu, s0, 2);
            s1 += __shfl_xor_sync(0xFFFFFFFFu, s1, 1);
            s1 += __shfl_xor_sync(0xFFFFFFFFu, s1, 2);
            float r0 = rsqrtf(s0 * (1.0f / HEAD_C) + RMS_EPS);
            float r1 = rsqrtf(s1 * (1.0f / HEAD_C) + RMS_EPS);
            #pragma unroll
            for (int nt = 0; nt < 4; nt++) {
                acc[mt][nt][0] *= r0; acc[mt][nt][1] *= r0;
                acc[mt][nt][2] *= r1; acc[mt][nt][3] *= r1;
            }
        }
        int r0 = m0 + wm + mt * 16 + (lane >> 2);
        int r1 = r0 + 8;
        #pragma unroll
        for (int nt = 0; nt < 4; nt++) {
            int col = n0 + wn + nt * 8 + (lane & 3) * 2 - colshift;
            if (r0 < Mrows)
                *(float2*)&outp[(size_t)r0 * HID + col] = make_float2(acc[mt][nt][0], acc[mt][nt][1]);
            if (r1 < Mrows)
                *(float2*)&outp[(size_t)r1 * HID + col] = make_float2(acc[mt][nt][2], acc[mt][nt][3]);
        }
    }
}

// ---------------- edge attention: one block per node, one warp per head ----
__global__ __launch_bounds__(256) void edge_kernel() {
    int i    = blockIdx.x;
    int h    = threadIdx.x >> 5;
    int lane = threadIdx.x & 31;

    int s = g_off[i];
    int e = g_off[i + 1];

    size_t qbase = (size_t)i * HID + h * HEAD_C + lane;
    float qv  = g_qn[qbase];
    float tot = 0.f;
    float acc = 0.f;
    const float scale = 0.17677669529663687f;  // 1/sqrt(32)

    for (int t = s; t < e; t++) {
        int j = g_col[t];
        size_t base = (size_t)j * HID + h * HEAD_C + lane;
        float kv = g_kn[base];
        float vv = g_v[base];
        float d = qv * kv;
        d += __shfl_xor_sync(0xFFFFFFFFu, d, 16);
        d += __shfl_xor_sync(0xFFFFFFFFu, d, 8);
        d += __shfl_xor_sync(0xFFFFFFFFu, d, 4);
        d += __shfl_xor_sync(0xFFFFFFFFu, d, 2);
        d += __shfl_xor_sync(0xFFFFFFFFu, d, 1);
        float w = __expf(d * scale);
        tot += w;
        acc = fmaf(w, vv, acc);
    }
    g_y[qbase] = (e > s) ? (acc / tot) : 0.f;
}

// ---------------- launch ---------------------------------------------------
extern "C" void kernel_launch(void* const* d_in, const int* in_sizes, int n_in,
                              void* d_out, int out_size) {
    const float* query = (const float*)d_in[0];
    const float* keys  = (const float*)d_in[1];
    const int*   edges = (const int*)d_in[2];
    const float* Wq    = (const float*)d_in[3];
    const float* bq    = (const float*)d_in[4];
    const float* Wkv   = (const float*)d_in[5];
    const float* bkv   = (const float*)d_in[6];
    const float* Wo    = (const float*)d_in[7];
    const float* bo    = (const float*)d_in[8];
    float* out = (float*)d_out;

    float* qn = nullptr; float* kn = nullptr; float* vv = nullptr; float* y = nullptr;
    int* degp = nullptr; int* curp = nullptr;
    cudaGetSymbolAddress((void**)&qn, g_qn);
    cudaGetSymbolAddress((void**)&kn, g_kn);
    cudaGetSymbolAddress((void**)&vv, g_v);
    cudaGetSymbolAddress((void**)&y,  g_y);
    cudaGetSymbolAddress((void**)&degp, g_deg);
    cudaGetSymbolAddress((void**)&curp, g_cur);

    const int SCAN_BLOCKS = (M_NODES + 1023) / 1024;  // 49

    // CSR build
    detect_kernel<<<1, 256>>>((const unsigned*)edges);
    cudaMemsetAsync(degp, 0, M_NODES * sizeof(int));
    cudaMemsetAsync(curp, 0, M_NODES * sizeof(int));
    count_edges<<<(E_EDGES + 255) / 256, 256>>>(edges);
    scan1_kernel<<<SCAN_BLOCKS, 1024>>>();
    scan2_kernel<<<1, 64>>>(SCAN_BLOCKS);
    scan3_kernel<<<SCAN_BLOCKS, 1024>>>();
    fill_edges<<<(E_EDGES + 255) / 256, 256>>>(edges);

    dim3 gq((M_NODES + BM - 1) / BM, HID / BN);       // 391 x 4
    dim3 gkv((N_NODES + BM - 1) / BM, 2 * HID / BN);  // 391 x 8

    // q projection + bias + RMS norm
    gemm_tc_kernel<<<gq, 256>>>(query, Wq, bq, qn, nullptr, M_NODES, 1);
    // kv projection + bias; k half normed -> kn, v half -> v
    gemm_tc_kernel<<<gkv, 256>>>(keys, Wkv, bkv, kn, vv, N_NODES, 2);
    // edge-softmax attention (CSR, no atomics)
    edge_kernel<<<M_NODES, 256>>>();
    // output projection
    gemm_tc_kernel<<<gq, 256>>>(y, Wo, bo, out, nullptr, M_NODES, 0);
}

// round 3
// speedup vs baseline: 2.1309x; 1.1678x over previous
#include <cuda_runtime.h>
#include <cstdint>

#define M_NODES 50000
#define N_NODES 50000
#define E_EDGES 800000
#define K_DIM   256
#define HID     256
#define HEADS   8
#define HEAD_C  32
#define RMS_EPS 1.1920929e-7f

// ---------------- scratch (static device arrays; no allocations) ----------
__device__ float g_qn[(size_t)M_NODES * HID];   // normalized q
__device__ float g_kn[(size_t)N_NODES * HID];   // normalized k
__device__ float g_v [(size_t)N_NODES * HID];   // v
__device__ float g_y [(size_t)M_NODES * HID];   // attention output
__device__ int   g_deg[M_NODES];
__device__ int   g_cur[M_NODES];
__device__ int   g_off[M_NODES + 1];
__device__ int   g_col[E_EDGES];
__device__ int   g_bsum[64];
__device__ int   g_is64;

// ---------------- edge dtype detection (int64 vs int32) -------------------
__global__ void detect_kernel(const unsigned* __restrict__ w) {
    __shared__ int nz;
    if (threadIdx.x == 0) nz = 0;
    __syncthreads();
    unsigned v = w[2 * threadIdx.x + 1];
    if (v != 0u) atomicAdd(&nz, 1);
    __syncthreads();
    if (threadIdx.x == 0) g_is64 = (nz == 0) ? 1 : 0;
}

// ---------------- CSR build ----------------------------------------------
__global__ void zero_kernel() {
    int i = blockIdx.x * blockDim.x + threadIdx.x;
    if (i < M_NODES) { g_deg[i] = 0; g_cur[i] = 0; }
}

__global__ void count_edges(const int* __restrict__ ew) {
    int e = blockIdx.x * blockDim.x + threadIdx.x;
    if (e >= E_EDGES) return;
    int i = g_is64 ? ew[4 * e] : ew[2 * e];
    atomicAdd(&g_deg[i], 1);
}

__global__ void scan1_kernel() {
    __shared__ int sh_warp[32];
    int lane = threadIdx.x & 31;
    int wid  = threadIdx.x >> 5;
    int idx  = blockIdx.x * 1024 + threadIdx.x;
    int v = (idx < M_NODES) ? g_deg[idx] : 0;
    int x = v;
    #pragma unroll
    for (int d = 1; d < 32; d <<= 1) {
        int t = __shfl_up_sync(0xFFFFFFFFu, x, d);
        if (lane >= d) x += t;
    }
    if (lane == 31) sh_warp[wid] = x;
    __syncthreads();
    if (wid == 0) {
        int y = sh_warp[lane];
        #pragma unroll
        for (int d = 1; d < 32; d <<= 1) {
            int t = __shfl_up_sync(0xFFFFFFFFu, y, d);
            if (lane >= d) y += t;
        }
        sh_warp[lane] = y;
    }
    __syncthreads();
    int incl = x + (wid > 0 ? sh_warp[wid - 1] : 0);
    if (idx < M_NODES) g_off[idx + 1] = incl;
    if (threadIdx.x == 1023) g_bsum[blockIdx.x] = incl;
}

__global__ void scan2_kernel(int nblk) {
    __shared__ int s[64];
    int t = threadIdx.x;
    int v = (t < nblk) ? g_bsum[t] : 0;
    s[t] = v;
    __syncthreads();
    #pragma unroll
    for (int d = 1; d < 64; d <<= 1) {
        int add = (t >= d) ? s[t - d] : 0;
        __syncthreads();
        s[t] += add;
        __syncthreads();
    }
    if (t < nblk) g_bsum[t] = s[t] - v;  // exclusive
}

__global__ void scan3_kernel() {
    int idx = blockIdx.x * 1024 + threadIdx.x;
    if (idx == 0) g_off[0] = 0;
    if (idx < M_NODES) g_off[idx + 1] += g_bsum[blockIdx.x];
}

__global__ void fill_edges(const int* __restrict__ ew) {
    int e = blockIdx.x * blockDim.x + threadIdx.x;
    if (e >= E_EDGES) return;
    int i, j;
    if (g_is64) { i = ew[4 * e]; j = ew[4 * e + 2]; }
    else        { i = ew[2 * e]; j = ew[2 * e + 1]; }
    int p = atomicAdd(&g_cur[i], 1);
    g_col[g_off[i] + p] = j;
}

// ---------------- TF32 tensor-core GEMM, cp.async 3-stage ------------------
// C[m,n] = sum_k A[m,k] * W[n,k] + bias[n]
// mode 0: plain -> outA; mode 1: norm all -> outA;
// mode 2: n<HID normed -> outA, n>=HID plain -> outB (cols shifted by HID)
#define BM 128
#define BN 128
#define BK 32
#define STAGES 3
#define A_STG (BM * BK)          // floats per A stage (4096)
#define B_STG (BN * BK)          // floats per B stage (4096)
#define GEMM_SMEM (STAGES * (A_STG + B_STG) * 4)

__device__ __forceinline__ unsigned f2tf32(float f) {
    unsigned r;
    asm("cvt.rna.tf32.f32 %0, %1;" : "=r"(r) : "f"(f));
    return r;
}

__device__ __forceinline__ void ldsm4(unsigned r[4], unsigned addr) {
    asm volatile("ldmatrix.sync.aligned.m8n8.x4.shared.b16 {%0,%1,%2,%3}, [%4];"
                 : "=r"(r[0]), "=r"(r[1]), "=r"(r[2]), "=r"(r[3]) : "r"(addr));
}

__device__ __forceinline__ void mma_tf32(float d[4], const unsigned a[4], const unsigned b[2]) {
    asm volatile(
        "mma.sync.aligned.m16n8k8.row.col.f32.tf32.tf32.f32 "
        "{%0,%1,%2,%3}, {%4,%5,%6,%7}, {%8,%9}, {%0,%1,%2,%3};\n"
        : "+f"(d[0]), "+f"(d[1]), "+f"(d[2]), "+f"(d[3])
        : "r"(a[0]), "r"(a[1]), "r"(a[2]), "r"(a[3]), "r"(b[0]), "r"(b[1]));
}

__device__ __forceinline__ void cp16(unsigned dst, const void* src, int sz) {
    asm volatile("cp.async.cg.shared.global [%0], [%1], 16, %2;\n"
                 :: "r"(dst), "l"(src), "r"(sz));
}
__device__ __forceinline__ void cp_commit() {
    asm volatile("cp.async.commit_group;\n");
}
template <int N>
__device__ __forceinline__ void cp_wait() {
    asm volatile("cp.async.wait_group %0;\n" :: "n"(N));
}

__global__ __launch_bounds__(256, 1) void gemm_tc_kernel(
    const float* __restrict__ A, const float* __restrict__ W,
    const float* __restrict__ bias,
    float* __restrict__ outA, float* __restrict__ outB,
    int Mrows, int mode)
{
    extern __shared__ float sm[];
    float* As = sm;
    float* Bs = sm + STAGES * A_STG;

    const int tid  = threadIdx.x;
    const int lane = tid & 31;
    const int wid  = tid >> 5;
    const int wm   = (wid & 3) * 32;    // warp m offset 0..96
    const int wn   = (wid >> 2) * 64;   // warp n offset 0/64
    const int m0   = blockIdx.x * BM;
    const int n0   = blockIdx.y * BN;

    const int g  = lane >> 3;
    const int lr = lane & 7;

    unsigned asb = (unsigned)__cvta_generic_to_shared(As);
    unsigned bsb = (unsigned)__cvta_generic_to_shared(Bs);

    const int rowA0 = wm + (g & 1) * 8 + lr;
    const int rowB0 = wn + (g >> 1) * 8 + lr;

    float acc[2][8][4];
    #pragma unroll
    for (int mt = 0; mt < 2; mt++)
        #pragma unroll
        for (int nt = 0; nt < 8; nt++)
            #pragma unroll
            for (int r = 0; r < 4; r++) acc[mt][nt][r] = 0.f;

    // per-thread cp.async chunk coords (4 chunks each for A and B per stage)
    // chunk id = q*256 + tid, row = id>>3, c16 = id&7, swizzled sc = c16 ^ (row&7)
    auto issue_stage = [&](int s) {
        int k0 = s * BK;
        int buf = s % STAGES;
        unsigned abase = asb + (unsigned)(buf * A_STG * 4);
        unsigned bbase = bsb + (unsigned)(buf * B_STG * 4);
        #pragma unroll
        for (int q = 0; q < 4; q++) {
            int id = q * 256 + tid;
            int row = id >> 3, c = id & 7;
            int sc = c ^ (row & 7);
            int gr = m0 + row;
            int sz = (gr < Mrows) ? 16 : 0;
            cp16(abase + (unsigned)(row * (BK * 4) + sc * 16),
                 &A[(size_t)gr * K_DIM + k0 + c * 4], sz);
        }
        #pragma unroll
        for (int q = 0; q < 4; q++) {
            int id = q * 256 + tid;
            int row = id >> 3, c = id & 7;
            int sc = c ^ (row & 7);
            cp16(bbase + (unsigned)(row * (BK * 4) + sc * 16),
                 &W[(size_t)(n0 + row) * K_DIM + k0 + c * 4], 16);
        }
        cp_commit();
    };

    const int NSTAGE = K_DIM / BK;  // 8
    issue_stage(0);
    issue_stage(1);

    for (int s = 0; s < NSTAGE; s++) {
        cp_wait<1>();          // stage s resident
        __syncthreads();
        if (s + 2 < NSTAGE) issue_stage(s + 2);
        else                cp_commit();   // keep group count aligned

        int buf = s % STAGES;
        unsigned abuf = asb + (unsigned)(buf * A_STG * 4);
        unsigned bbuf = bsb + (unsigned)(buf * B_STG * 4);

        #pragma unroll
        for (int ks = 0; ks < 4; ks++) {
            unsigned af[2][4], bf[8][2];
            int cA = ks * 2 + (g >> 1);
            int cB = ks * 2 + (g & 1);
            #pragma unroll
            for (int mt = 0; mt < 2; mt++) {
                int row = rowA0 + mt * 16;
                unsigned addr = abuf + (unsigned)((row * BK + ((cA ^ (row & 7)) * 4)) * 4);
                ldsm4(af[mt], addr);
                #pragma unroll
                for (int r = 0; r < 4; r++)
                    af[mt][r] = f2tf32(__uint_as_float(af[mt][r]));
            }
            #pragma unroll
            for (int bt = 0; bt < 4; bt++) {
                int row = rowB0 + bt * 16;
                unsigned addr = bbuf + (unsigned)((row * BK + ((cB ^ (row & 7)) * 4)) * 4);
                unsigned q4[4];
                ldsm4(q4, addr);
                #pragma unroll
                for (int r = 0; r < 4; r++)
                    q4[r] = f2tf32(__uint_as_float(q4[r]));
                bf[bt * 2 + 0][0] = q4[0]; bf[bt * 2 + 0][1] = q4[1];
                bf[bt * 2 + 1][0] = q4[2]; bf[bt * 2 + 1][1] = q4[3];
            }
            #pragma unroll
            for (int mt = 0; mt < 2; mt++)
                #pragma unroll
                for (int nt = 0; nt < 8; nt++)
                    mma_tf32(acc[mt][nt], af[mt], bf[nt]);
        }
        __syncthreads();
    }

    // ---------------- epilogue: bias, per-head RMS norm, store -------------
    bool donorm = (mode == 1) || (mode == 2 && n0 < HID);
    bool toB    = (mode == 2) && (n0 >= HID);
    float* outp = toB ? outB : outA;
    int colshift = toB ? HID : 0;

    float bb[8][2];
    #pragma unroll
    for (int nt = 0; nt < 8; nt++) {
        int col = n0 + wn + nt * 8 + (lane & 3) * 2;
        bb[nt][0] = bias[col];
        bb[nt][1] = bias[col + 1];
    }

    #pragma unroll
    for (int mt = 0; mt < 2; mt++) {
        #pragma unroll
        for (int nt = 0; nt < 8; nt++) {
            acc[mt][nt][0] += bb[nt][0];
            acc[mt][nt][1] += bb[nt][1];
            acc[mt][nt][2] += bb[nt][0];
            acc[mt][nt][3] += bb[nt][1];
        }
        if (donorm) {
            #pragma unroll
            for (int ch = 0; ch < 2; ch++) {   // two 32-col head chunks per warp tile
                float s0 = 0.f, s1 = 0.f;
                #pragma unroll
                for (int nt = ch * 4; nt < ch * 4 + 4; nt++) {
                    s0 += acc[mt][nt][0] * acc[mt][nt][0] + acc[mt][nt][1] * acc[mt][nt][1];
                    s1 += acc[mt][nt][2] * acc[mt][nt][2] + acc[mt][nt][3] * acc[mt][nt][3];
                }
                s0 += __shfl_xor_sync(0xFFFFFFFFu, s0, 1);
                s0 += __shfl_xor_sync(0xFFFFFFFFu, s0, 2);
                s1 += __shfl_xor_sync(0xFFFFFFFFu, s1, 1);
                s1 += __shfl_xor_sync(0xFFFFFFFFu, s1, 2);
                float r0 = rsqrtf(s0 * (1.0f / HEAD_C) + RMS_EPS);
                float r1 = rsqrtf(s1 * (1.0f / HEAD_C) + RMS_EPS);
                #pragma unroll
                for (int nt = ch * 4; nt < ch * 4 + 4; nt++) {
                    acc[mt][nt][0] *= r0; acc[mt][nt][1] *= r0;
                    acc[mt][nt][2] *= r1; acc[mt][nt][3] *= r1;
                }
            }
        }
        int r0 = m0 + wm + mt * 16 + (lane >> 2);
        int r1 = r0 + 8;
        #pragma unroll
        for (int nt = 0; nt < 8; nt++) {
            int col = n0 + wn + nt * 8 + (lane & 3) * 2 - colshift;
            if (r0 < Mrows)
                *(float2*)&outp[(size_t)r0 * HID + col] = make_float2(acc[mt][nt][0], acc[mt][nt][1]);
            if (r1 < Mrows)
                *(float2*)&outp[(size_t)r1 * HID + col] = make_float2(acc[mt][nt][2], acc[mt][nt][3]);
        }
    }
}

// -------- edge attention: block per node, warp per head, 4 edges/iter ------
__global__ __launch_bounds__(256) void edge_kernel() {
    int i    = blockIdx.x;
    int h    = threadIdx.x >> 5;
    int lane = threadIdx.x & 31;
    int q4   = lane & 7;      // 16B chunk within head
    int sub  = lane >> 3;     // edge subgroup 0..3

    int s = g_off[i];
    int e = g_off[i + 1];

    size_t hb = (size_t)i * HID + h * HEAD_C;
    if (e <= s) {
        if (sub == 0) *(float4*)&g_y[hb + q4 * 4] = make_float4(0.f, 0.f, 0.f, 0.f);
        return;
    }

    float4 qf = *(const float4*)&g_qn[hb + q4 * 4];
    float4 acc = make_float4(0.f, 0.f, 0.f, 0.f);
    float tot = 0.f;
    const float scale = 0.17677669529663687f;  // 1/sqrt(32)

    for (int t0 = s; t0 < e; t0 += 4) {
        int t  = t0 + sub;
        int tc = min(t, e - 1);
        int j  = g_col[tc];
        const float* base = &g_kn[(size_t)j * HID + h * HEAD_C + q4 * 4];
        float4 kf = *(const float4*)base;
        float4 vf = *(const float4*)&g_v[(size_t)j * HID + h * HEAD_C + q4 * 4];
        float d = qf.x * kf.x + qf.y * kf.y + qf.z * kf.z + qf.w * kf.w;
        d += __shfl_xor_sync(0xFFFFFFFFu, d, 1);
        d += __shfl_xor_sync(0xFFFFFFFFu, d, 2);
        d += __shfl_xor_sync(0xFFFFFFFFu, d, 4);
        float w = (t < e) ? __expf(d * scale) : 0.f;
        tot += w;
        acc.x = fmaf(w, vf.x, acc.x);
        acc.y = fmaf(w, vf.y, acc.y);
        acc.z = fmaf(w, vf.z, acc.z);
        acc.w = fmaf(w, vf.w, acc.w);
    }
    // reduce across the 4 edge subgroups (lanes xor 8, 16)
    #pragma unroll
    for (int m = 8; m <= 16; m <<= 1) {
        acc.x += __shfl_xor_sync(0xFFFFFFFFu, acc.x, m);
        acc.y += __shfl_xor_sync(0xFFFFFFFFu, acc.y, m);
        acc.z += __shfl_xor_sync(0xFFFFFFFFu, acc.z, m);
        acc.w += __shfl_xor_sync(0xFFFFFFFFu, acc.w, m);
        tot   += __shfl_xor_sync(0xFFFFFFFFu, tot,   m);
    }
    if (sub == 0) {
        float inv = 1.0f / tot;
        *(float4*)&g_y[hb + q4 * 4] =
            make_float4(acc.x * inv, acc.y * inv, acc.z * inv, acc.w * inv);
    }
}

// ---------------- launch ---------------------------------------------------
extern "C" void kernel_launch(void* const* d_in, const int* in_sizes, int n_in,
                              void* d_out, int out_size) {
    const float* query = (const float*)d_in[0];
    const float* keys  = (const float*)d_in[1];
    const int*   edges = (const int*)d_in[2];
    const float* Wq    = (const float*)d_in[3];
    const float* bq    = (const float*)d_in[4];
    const float* Wkv   = (const float*)d_in[5];
    const float* bkv   = (const float*)d_in[6];
    const float* Wo    = (const float*)d_in[7];
    const float* bo    = (const float*)d_in[8];
    float* out = (float*)d_out;

    float* qn = nullptr; float* kn = nullptr; float* vv = nullptr; float* y = nullptr;
    cudaGetSymbolAddress((void**)&qn, g_qn);
    cudaGetSymbolAddress((void**)&kn, g_kn);
    cudaGetSymbolAddress((void**)&vv, g_v);
    cudaGetSymbolAddress((void**)&y,  g_y);

    cudaFuncSetAttribute(gemm_tc_kernel,
                         cudaFuncAttributeMaxDynamicSharedMemorySize, GEMM_SMEM);

    const int SCAN_BLOCKS = (M_NODES + 1023) / 1024;  // 49
    dim3 gq((M_NODES + BM - 1) / BM, HID / BN);        // 391 x 2
    dim3 gkv((N_NODES + BM - 1) / BM, 2 * HID / BN);   // 391 x 4

    // launch order arranged so ncu (-s 5 -c 1) captures gemm_kv (launch #6)
    detect_kernel<<<1, 256>>>((const unsigned*)edges);                     // 1
    zero_kernel<<<SCAN_BLOCKS, 1024>>>();                                  // 2
    count_edges<<<(E_EDGES + 255) / 256, 256>>>(edges);                    // 3
    scan1_kernel<<<SCAN_BLOCKS, 1024>>>();                                 // 4
    gemm_tc_kernel<<<gq, 256, GEMM_SMEM>>>(query, Wq, bq, qn, nullptr,
                                           M_NODES, 1);                    // 5
    gemm_tc_kernel<<<gkv, 256, GEMM_SMEM>>>(keys, Wkv, bkv, kn, vv,
                                            N_NODES, 2);                   // 6  <- ncu
    scan2_kernel<<<1, 64>>>(SCAN_BLOCKS);                                  // 7
    scan3_kernel<<<SCAN_BLOCKS, 1024>>>();                                 // 8
    fill_edges<<<(E_EDGES + 255) / 256, 256>>>(edges);                     // 9
    edge_kernel<<<M_NODES, 256>>>();                                       // 10
    gemm_tc_kernel<<<gq, 256, GEMM_SMEM>>>(y, Wo, bo, out, nullptr,
                                           M_NODES, 0);                    // 11
}